// round 17
// baseline (speedup 1.0000x reference)
#include <cuda_runtime.h>
#include <cuda_fp16.h>
#include <cuda_bf16.h>

// Problem constants: B=8, C=64, H=W=128, G=2, D=32, K=9, OS=2.0
#define PB 16384
#define NB 8
#define NROWS (NB * PB)
#define TAB (NB * 2 * PB * 32)   // element offset of the shifted (B) value table

// Merged value table, fp16, group-major: [parity][b][g][p][32ch].
__device__ __half g_val[2 * NB * 2 * PB * 32];
__device__ float g_om[NB * PB * 54];      // (b,p,54)
// HMMA B-fragment tables (lane order: n = base + (lane>>2), k0 = kc*16 + 2*(lane&3)).
__device__ uint2 g_omwh[896];             // om: 7 n-tiles x 4 kc x 32 lanes {b0,b1}
__device__ uint2 g_opwh[1024];            // op: 8 n-tiles x 4 kc x 32 lanes
__device__ uint4 g_vpwh[1024];            // vp: 8 n-tiles x 4 kc x 32 lanes {bh0,bh1,bl0,bl1}

#define SW2(r) (((r) & 7) << 2)           // swizzle for half2 index

__device__ __forceinline__ void mmah(float* c, unsigned a0, unsigned a1,
                                     unsigned a2, unsigned a3,
                                     unsigned b0, unsigned b1) {
    asm("mma.sync.aligned.m16n8k16.row.col.f32.f16.f16.f32 "
        "{%0,%1,%2,%3},{%4,%5,%6,%7},{%8,%9},{%0,%1,%2,%3};"
        : "+f"(c[0]), "+f"(c[1]), "+f"(c[2]), "+f"(c[3])
        : "r"(a0), "r"(a1), "r"(a2), "r"(a3), "r"(b0), "r"(b1));
}
__device__ __forceinline__ unsigned packh2(float a, float b) {
    __half2 h = __floats2half2_rn(a, b);
    return *reinterpret_cast<unsigned*>(&h);
}
// fp16 hi/lo split of a float pair (residual <= 2^-11 -> 3-term product is fp32-class).
__device__ __forceinline__ void split_h2(float a, float b, unsigned& hi, unsigned& lo) {
    __half2 h = __floats2half2_rn(a, b);
    float2 hf = __half22float2(h);
    __half2 l = __floats2half2_rn(a - hf.x, b - hf.y);
    hi = *reinterpret_cast<unsigned*>(&h);
    lo = *reinterpret_cast<unsigned*>(&l);
}

// ---------------------------------------------------------------------------
// K0: prepack om_w / op_w (fp16) and vp_w (fp16 hi/lo) into HMMA fragment order.
// ---------------------------------------------------------------------------
__global__ void __launch_bounds__(256) k0_split(const float* __restrict__ om_w,
                                                const float* __restrict__ op_w,
                                                const float* __restrict__ vp_w) {
    int i = blockIdx.x * 256 + threadIdx.x;
    if (i < 896) {
        int w = i >> 7, rem = i & 127, kc = rem >> 5, lane = rem & 31;
        int n = w * 8 + (lane >> 2), k0 = kc * 16 + 2 * (lane & 3);
        float f0 = (n < 54) ? om_w[n * 64 + k0] : 0.f;
        float f1 = (n < 54) ? om_w[n * 64 + k0 + 1] : 0.f;
        float f2 = (n < 54) ? om_w[n * 64 + k0 + 8] : 0.f;
        float f3 = (n < 54) ? om_w[n * 64 + k0 + 9] : 0.f;
        g_omwh[i] = make_uint2(packh2(f0, f1), packh2(f2, f3));
    } else if (i < 1920) {
        int j = i - 896;
        int w = j >> 7, rem = j & 127, kc = rem >> 5, lane = rem & 31;
        int n = w * 8 + (lane >> 2), k0 = kc * 16 + 2 * (lane & 3);
        g_opwh[j] = make_uint2(
            packh2(op_w[n * 64 + k0], op_w[n * 64 + k0 + 1]),
            packh2(op_w[n * 64 + k0 + 8], op_w[n * 64 + k0 + 9]));
    } else if (i < 2944) {
        int j = i - 1920;
        int nt = j >> 7, rem = j & 127, kc = rem >> 5, lane = rem & 31;
        int n = nt * 8 + (lane >> 2), k0 = kc * 16 + 2 * (lane & 3);
        unsigned h0, l0, h1, l1;
        split_h2(vp_w[n * 64 + k0], vp_w[n * 64 + k0 + 1], h0, l0);
        split_h2(vp_w[n * 64 + k0 + 8], vp_w[n * 64 + k0 + 9], h1, l1);
        g_vpwh[j] = make_uint4(h0, h1, l0, l1);
    }
}

// ---------------------------------------------------------------------------
// K12: FUSED conv + om GEMM + value projection. Block = 64 px of one image
// row. Phase A: depthwise conv -> d2 smem (fp16). Phase V: value projection
// via 3-term fp16-split HMMA, A-fragments from x (L1-hot after conv). Phase
// B: om GEMM (warps 0-6). x is read once per tile instead of twice per launch.
// ---------------------------------------------------------------------------
__global__ void __launch_bounds__(256) k12_fused(const float* __restrict__ x,
                                                 const float* __restrict__ dw_w,
                                                 const float* __restrict__ dw_b,
                                                 const float* __restrict__ om_b,
                                                 const float* __restrict__ vp_b) {
    __shared__ unsigned d2[2048];     // 64 px x 32 half2, swizzled
    int t = threadIdx.x;

    int bb = blockIdx.x >> 8;
    int p0 = (blockIdx.x & 255) * 64;
    int h = p0 >> 7;
    int w0 = p0 & 127;
    const float* xb = x + (size_t)bb * (PB * 64);

    // ---- Phase A: depthwise conv (sliding window) ----
    {
        int c = t & 63;
        int pg = t >> 6;
        float wk[9];
#pragma unroll
        for (int k = 0; k < 9; k++) wk[k] = dw_w[c * 9 + k];
        float bias = dw_b[c];
        int wstart = w0 + pg * 16;
        const float* xc = xb + c;
        float v[3][3];
#pragma unroll
        for (int ky = 0; ky < 3; ky++) {
            int yy = h + ky - 1;
            bool yok = (unsigned)yy < 128u;
            int xm1 = wstart - 1;
            v[ky][1] = (yok && (unsigned)xm1 < 128u)
                           ? __ldg(xc + ((size_t)((yy << 7) + xm1) << 6)) : 0.f;
            v[ky][2] = yok ? __ldg(xc + ((size_t)((yy << 7) + wstart) << 6)) : 0.f;
        }
        int c2 = c >> 1, cl = c & 1;
        for (int i = 0; i < 16; i++) {
            int w = wstart + i;
            int xp1 = w + 1;
#pragma unroll
            for (int ky = 0; ky < 3; ky++) {
                int yy = h + ky - 1;
                v[ky][0] = v[ky][1];
                v[ky][1] = v[ky][2];
                v[ky][2] = ((unsigned)yy < 128u && (unsigned)xp1 < 128u)
                               ? __ldg(xc + ((size_t)((yy << 7) + xp1) << 6)) : 0.f;
            }
            float acc = bias;
#pragma unroll
            for (int ky = 0; ky < 3; ky++)
#pragma unroll
                for (int kx = 0; kx < 3; kx++)
                    acc = fmaf(v[ky][kx], wk[ky * 3 + kx], acc);
            int px = pg * 16 + i;
            int idx = px * 32 + (c2 ^ SW2(px));
            ((__half*)d2)[idx * 2 + cl] = __float2half_rn(acc);
        }
    }
    __syncthreads();

    // ---- Phase V: value projection for the 64 rows of this tile ----
    {
        int w = t >> 5, lane = t & 31;
        int r = lane >> 2, q = lane & 3;
        int mt = w & 3;                  // m-tile (16 rows)
        int nth = w >> 2;                // n half (4 n-tiles each)
        int pA = p0 + mt * 16 + r;       // row within batch
        const float* arA = xb + (size_t)pA * 64;

        float acc[4][4];
#pragma unroll
        for (int ntl = 0; ntl < 4; ntl++)
#pragma unroll
            for (int i = 0; i < 4; i++) acc[ntl][i] = 0.f;

#pragma unroll
        for (int kc = 0; kc < 4; kc++) {
            int k0e = kc * 16 + 2 * q;
            float2 fA0 = __ldg((const float2*)(arA + k0e));
            float2 fB0 = __ldg((const float2*)(arA + 512 + k0e));
            float2 fA1 = __ldg((const float2*)(arA + k0e + 8));
            float2 fB1 = __ldg((const float2*)(arA + 512 + k0e + 8));
            unsigned ah0, al0, ah1, al1, ah2, al2, ah3, al3;
            split_h2(fA0.x, fA0.y, ah0, al0);
            split_h2(fB0.x, fB0.y, ah1, al1);
            split_h2(fA1.x, fA1.y, ah2, al2);
            split_h2(fB1.x, fB1.y, ah3, al3);
            const uint4* bw = g_vpwh + kc * 32 + lane + (size_t)nth * 512;
#pragma unroll
            for (int ntl = 0; ntl < 4; ntl++) {
                uint4 bv = __ldg(bw + ntl * 128);
                mmah(acc[ntl], ah0, ah1, ah2, ah3, bv.x, bv.y);   // hi*hi
                mmah(acc[ntl], ah0, ah1, ah2, ah3, bv.z, bv.w);   // hi*lo
                mmah(acc[ntl], al0, al1, al2, al3, bv.x, bv.y);   // lo*hi
            }
        }

        int xA = pA & 127;
        int xB = (pA + 8) & 127;
        size_t gb0 = (size_t)(bb * 2) * 16384;
#pragma unroll
        for (int ntl = 0; ntl < 4; ntl++) {
            int nt = nth * 4 + ntl;
            int jc = nt * 8 + 2 * q;
            float2 b2 = __ldg((const float2*)(vp_b + jc));
            int g = jc >> 5;
            int ch = jc & 31;
            __half2 h0 = __floats2half2_rn(acc[ntl][0] + b2.x, acc[ntl][1] + b2.y);
            __half2 h1 = __floats2half2_rn(acc[ntl][2] + b2.x, acc[ntl][3] + b2.y);
            size_t pxb = (gb0 + (size_t)g * 16384 + pA) * 32 + ch;
            *(__half2*)&g_val[pxb] = h0;
            *(__half2*)&g_val[pxb + 256] = h1;                  // row +8
            if (xA >= 1) *(__half2*)&g_val[TAB + pxb - 32] = h0;
            if (xB >= 1) *(__half2*)&g_val[TAB + pxb + 224] = h1;
        }
    }

    // ---- Phase B: om GEMM (warps 0-6; d2 unchanged since the sync) ----
    int w = t >> 5;
    if (w < 7) {
        int lane = t & 31;
        int r = lane >> 2, q = lane & 3;
        float acc[4][4];
#pragma unroll
        for (int mt = 0; mt < 4; mt++)
#pragma unroll
            for (int i = 0; i < 4; i++) acc[mt][i] = 0.f;
        const uint2* bw = g_omwh + w * 128 + lane;
#pragma unroll
        for (int kc = 0; kc < 4; kc++) {
            uint2 bv = __ldg(bw + kc * 32);
            int k8 = kc * 8 + q;
#pragma unroll
            for (int mt = 0; mt < 4; mt++) {
                int rA = mt * 16 + r, rB = rA + 8;
                unsigned a0 = d2[rA * 32 + (k8 ^ SW2(rA))];
                unsigned a1 = d2[rB * 32 + (k8 ^ SW2(rB))];
                unsigned a2 = d2[rA * 32 + ((k8 + 4) ^ SW2(rA))];
                unsigned a3 = d2[rB * 32 + ((k8 + 4) ^ SW2(rB))];
                mmah(acc[mt], a0, a1, a2, a3, bv.x, bv.y);
            }
        }
        int jc = w * 8 + 2 * q;
        if (jc < 54) {
            float2 ob2 = __ldg((const float2*)(om_b + jc));
#pragma unroll
            for (int mt = 0; mt < 4; mt++) {
                int pxA = p0 + mt * 16 + r;
                size_t baseA = ((size_t)bb * PB + pxA) * 54;
                *(float2*)&g_om[baseA + jc] =
                    make_float2(acc[mt][0] + ob2.x, acc[mt][1] + ob2.y);
                *(float2*)&g_om[baseA + 54 * 8 + jc] =
                    make_float2(acc[mt][2] + ob2.x, acc[mt][3] + ob2.y);
            }
        }
    }
}

// ---------------------------------------------------------------------------
// K3: DCN (r14 version: precomputed geometry, scalar-cvt fp32-accum gather,
// fp16 HMMA op GEMM, in-register fold + BN + ReLU).
// ---------------------------------------------------------------------------
__global__ void __launch_bounds__(256) k3_dcn(const float* __restrict__ op_b,
                                              const float* __restrict__ bn_g,
                                              const float* __restrict__ bn_b,
                                              const float* __restrict__ bn_m,
                                              const float* __restrict__ bn_v,
                                              float* __restrict__ out) {
    __shared__ __align__(8) float2 s_wp[1152];   // [it][side] = (wTop, wBot)
    __shared__ int s_lin[576];                   // full element offset (incl. parity)
    __shared__ __align__(16) unsigned s_c[1024]; // 32 px x 32 half2, swizzled
    int t = threadIdx.x;

    int bb = blockIdx.x >> 9;
    int p0 = (blockIdx.x & 511) * 16;        // in [0, 8192)

    // Phase W: 32 px x 2 g x 9 k = 576 geometry items.
    for (int it = t; it < 576; it += 256) {
        int pl = it / 18;
        int rem = it - pl * 18;
        int g = rem / 9;
        int k = rem - g * 9;
        int p = p0 + ((pl < 16) ? pl : (pl - 16 + 8192));
        int h = p >> 7, w = p & 127;
        const float* om = g_om + ((size_t)bb * PB + p) * 54 + g * 27;
        float ox = om[2 * k], oy = om[2 * k + 1], m = om[18 + k];
        float ix = (float)w + ((float)(k - (k / 3) * 3) - 1.0f + ox) * 2.0f;
        float iy = (float)h + ((float)(k / 3) - 1.0f + oy) * 2.0f;
        float xf = floorf(ix), yf = floorf(iy);
        float tx = ix - xf, ty = iy - yf;
        int x0 = (int)xf, y0 = (int)yf;
        float wx0 = ((unsigned)x0 < 128u) ? (1.f - tx) : 0.f;
        float wx1 = ((unsigned)(x0 + 1) < 128u) ? tx : 0.f;
        int x0c = x0;
        if (x0 < 0)        { wx0 = wx1; wx1 = 0.f; x0c = 0; }
        else if (x0 > 126) { wx1 = wx0; wx0 = 0.f; x0c = 126; }
        float wy0 = ((unsigned)y0 < 128u) ? (1.f - ty) : 0.f;
        float wy1 = ((unsigned)(y0 + 1) < 128u) ? ty : 0.f;
        int y0c = y0;
        if (y0 < 0)        { wy0 = wy1; wy1 = 0.f; y0c = 0; }
        else if (y0 > 126) { wy1 = wy0; wy0 = 0.f; y0c = 126; }
        s_lin[it] = ((x0c & 1) ? TAB : 0) + ((y0c << 7) + (x0c & ~1)) * 32;
        s_wp[it * 2 + 0] = make_float2(wy0 * wx0 * m, wy1 * wx0 * m);  // left
        s_wp[it * 2 + 1] = make_float2(wy0 * wx1 * m, wy1 * wx1 * m);  // right
    }
    __syncthreads();

    // Gather: 8 lanes per (pixel, group); lanes 0-3 left corner, 4-7 right.
    {
        int lane = t & 31;
        int l8 = lane & 7;
        int side = l8 >> 2;
        int cq = l8 & 3;
        int sg_id = t >> 3;
#pragma unroll
        for (int pass = 0; pass < 2; pass++) {
            int sgg = sg_id + pass * 32;     // 0..63
            int pl = sgg >> 1;
            int g = sgg & 1;
            int ib = pl * 18 + g * 9;
            const __half* vb = g_val + (size_t)(bb * 2 + g) * (PB * 32) + l8 * 8;
            float acc[8] = {0.f, 0.f, 0.f, 0.f, 0.f, 0.f, 0.f, 0.f};
#pragma unroll
            for (int k = 0; k < 9; k++) {
                int off = s_lin[ib + k];
                float2 wp = s_wp[(ib + k) * 2 + side];
                const __half* base = vb + off;
                uint4 tv = __ldg((const uint4*)base);
                uint4 bv = __ldg((const uint4*)(base + 4096));
#define GACC(u, wgt, i0) do { \
    float2 f_ = __half22float2(*reinterpret_cast<const __half2*>(&(u))); \
    acc[i0] = fmaf((wgt), f_.x, acc[i0]); \
    acc[i0 + 1] = fmaf((wgt), f_.y, acc[i0 + 1]); } while (0)
                GACC(tv.x, wp.x, 0); GACC(tv.y, wp.x, 2);
                GACC(tv.z, wp.x, 4); GACC(tv.w, wp.x, 6);
                GACC(bv.x, wp.y, 0); GACC(bv.y, wp.y, 2);
                GACC(bv.z, wp.y, 4); GACC(bv.w, wp.y, 6);
#undef GACC
            }
#pragma unroll
            for (int i = 0; i < 8; i++)
                acc[i] += __shfl_xor_sync(0xFFFFFFFFu, acc[i], 4);
            if (side == 0) {
                int c2 = g * 16 + cq * 4;
                int idx = pl * 32 + (c2 ^ SW2(pl));
                uint4 v;
                v.x = packh2(acc[0], acc[1]);
                v.y = packh2(acc[2], acc[3]);
                v.z = packh2(acc[4], acc[5]);
                v.w = packh2(acc[6], acc[7]);
                *(uint4*)&s_c[idx] = v;
            }
        }
    }
    __syncthreads();

    // op GEMM via fp16 HMMA: warp w -> n-tile w; m-tiles rows 0-15 / 16-31.
    {
        int w = t >> 5, lane = t & 31;
        int r = lane >> 2, q = lane & 3;
        float accA[4] = {0.f, 0.f, 0.f, 0.f};
        float accB[4] = {0.f, 0.f, 0.f, 0.f};
        const uint2* bw = g_opwh + w * 128 + lane;
#pragma unroll
        for (int kc = 0; kc < 4; kc++) {
            uint2 bv = __ldg(bw + kc * 32);
            int k8 = kc * 8 + q;
            {
                int rA = r, rB = r + 8;
                unsigned a0 = s_c[rA * 32 + (k8 ^ SW2(rA))];
                unsigned a1 = s_c[rB * 32 + (k8 ^ SW2(rB))];
                unsigned a2 = s_c[rA * 32 + ((k8 + 4) ^ SW2(rA))];
                unsigned a3 = s_c[rB * 32 + ((k8 + 4) ^ SW2(rB))];
                mmah(accA, a0, a1, a2, a3, bv.x, bv.y);
            }
            {
                int rA = 16 + r, rB = 24 + r;
                unsigned a0 = s_c[rA * 32 + (k8 ^ SW2(rA))];
                unsigned a1 = s_c[rB * 32 + (k8 ^ SW2(rB))];
                unsigned a2 = s_c[rA * 32 + ((k8 + 4) ^ SW2(rA))];
                unsigned a3 = s_c[rB * 32 + ((k8 + 4) ^ SW2(rB))];
                mmah(accB, a0, a1, a2, a3, bv.x, bv.y);
            }
        }
        int jc = w * 8 + 2 * q;
        float2 ob2 = __ldg((const float2*)(op_b + jc));
        int cz = p0 >> 8;
        float sA = __ldg(bn_g + cz) * rsqrtf(__ldg(bn_v + cz) + 1e-5f);
        float sB = fmaf(-sA, __ldg(bn_m + cz), __ldg(bn_b + cz));
#pragma unroll
        for (int half = 0; half < 2; half++) {
            int rr = r + half * 8;
            int i0 = half * 2, i1 = half * 2 + 1;
            int p = p0 + rr;
            float z0 = fmaf(0.5f * (accA[i0] + accB[i0]) + ob2.x, sA, sB);
            float z1 = fmaf(0.5f * (accA[i1] + accB[i1]) + ob2.y, sA, sB);
            int hh = (p >> 1) & 127;
            int qq = p & 1;
            size_t base = (((size_t)bb * 32 + cz) * 128 + hh) * 128 + (qq << 6);
            *(float2*)&out[base + jc] =
                make_float2(fmaxf(z0, 0.f), fmaxf(z1, 0.f));
        }
    }
}

// ---------------------------------------------------------------------------
extern "C" void kernel_launch(void* const* d_in, const int* in_sizes, int n_in,
                              void* d_out, int out_size) {
    const float* x    = (const float*)d_in[0];
    const float* vp_w = (const float*)d_in[1];
    const float* vp_b = (const float*)d_in[2];
    const float* dw_w = (const float*)d_in[3];
    const float* dw_b = (const float*)d_in[4];
    const float* om_w = (const float*)d_in[5];
    const float* om_b = (const float*)d_in[6];
    const float* op_w = (const float*)d_in[7];
    const float* op_b = (const float*)d_in[8];
    const float* bn_g = (const float*)d_in[9];
    const float* bn_b = (const float*)d_in[10];
    const float* bn_m = (const float*)d_in[11];
    const float* bn_v = (const float*)d_in[12];
    float* out = (float*)d_out;

    k0_split<<<12, 256>>>(om_w, op_w, vp_w);
    k12_fused<<<NB * (PB / 64), 256>>>(x, dw_w, dw_b, om_b, vp_b);
    k3_dcn<<<NB * 512, 256>>>(op_b, bn_g, bn_b, bn_m, bn_v, out);
}